// round 3
// baseline (speedup 1.0000x reference)
#include <cuda_runtime.h>

#define NC 16       // codebooks
#define NK 16       // prototypes per codebook
#define NM 16       // output rows (M)
#define ND 64       // feature dim
#define NSPL 4      // tree depth
#define LSTR 20     // LUT row stride: quad-bank (5g+j)%8 bijective in g&7 -> conflict-free LDS.128
#define TB 256      // threads = rows per tile

__device__ float g_lut[NC * NK * NM];

// ---------------------------------------------------------------------------
// Kernel 1: lut[c,k,m] = sum_d B[m,d] * prototypes[c,k,d]
// ---------------------------------------------------------------------------
__global__ void lut_kernel(const float* __restrict__ B, const float* __restrict__ P) {
    __shared__ float Bs[NM][ND + 1];
    __shared__ float Ps[NK][ND + 1];
    int c = blockIdx.x, tid = threadIdx.x;
    for (int i = tid; i < NM * ND; i += 256) Bs[i >> 6][i & 63] = B[i];
    for (int i = tid; i < NK * ND; i += 256) Ps[i >> 6][i & 63] = P[c * NK * ND + i];
    __syncthreads();
    int k = tid >> 4, m = tid & 15;
    float acc = 0.f;
#pragma unroll
    for (int d = 0; d < ND; d++) acc = fmaf(Bs[m][d], Ps[k][d], acc);
    g_lut[(c * NK + k) * NM + m] = acc;
}

// ---------------------------------------------------------------------------
// cp.async helpers
// ---------------------------------------------------------------------------
__device__ __forceinline__ unsigned smem_u32(const void* p) {
    unsigned a;
    asm("{ .reg .u64 t; cvta.to.shared.u64 t, %1; cvt.u32.u64 %0, t; }" : "=r"(a) : "l"(p));
    return a;
}
__device__ __forceinline__ void cpa16(unsigned dst, const void* src) {
    asm volatile("cp.async.cg.shared.global [%0], [%1], 16;\n" :: "r"(dst), "l"(src));
}
__device__ __forceinline__ void cpa_commit() { asm volatile("cp.async.commit_group;\n"); }
__device__ __forceinline__ void cpa_wait0()  { asm volatile("cp.async.wait_group 0;\n"); }

__device__ __forceinline__ void fadd2(unsigned long long& a, unsigned long long b) {
    asm("add.rn.f32x2 %0, %0, %1;" : "+l"(a) : "l"(b));
}

// ---------------------------------------------------------------------------
// Kernel 2: one 256-row tile per CTA, 2 CTAs/SM.
// A tile: 16B chunk ch of row r stored at slot (ch ^ (r&15)) -> coalesced
// cp.async, encode reads <=2-way conflicted.
// LUT: stride-20 rows, float4 gather conflict-free across distinct gids.
// ---------------------------------------------------------------------------
__global__ void __launch_bounds__(TB, 2) maddness_kernel(
    const float* __restrict__ A,
    const int*   __restrict__ sdim_g,   // [C,NSPL]
    const float* __restrict__ sval_g,   // [C,NSPL,8]
    float*       __restrict__ out,      // [M,N]
    int N)
{
    extern __shared__ float smem[];
    float* As    = smem;                              // TB*ND floats (64KB, 16B aligned)
    float* lut_s = As + TB * ND;                      // NC*NK*LSTR = 5120 floats
    float* sval  = lut_s + NC * NK * LSTR;            // 512 floats
    int*   sdim  = (int*)(sval + NC * NSPL * 8);      // 64 ints

    const int tid = threadIdx.x;
    const long long base = (long long)blockIdx.x * TB;
    const long long Nll = N;

    // --- A tile: 16 x 16B cp.async per thread, coalesced, 16B-granule swizzle ---
    {
        const unsigned As_u = smem_u32(As);
        const float* gb = A + base * ND;
#pragma unroll
        for (int j = 0; j < 16; j++) {
            int idx = j * TB + tid;          // 16B-chunk index in tile
            int r   = idx >> 4;              // row 0..255
            int ch  = idx & 15;              // chunk 0..15
            if (base + r < N)
                cpa16(As_u + (unsigned)(r * ND + ((ch ^ (r & 15)) << 2)) * 4,
                      gb + (long long)r * ND + ch * 4);
        }
        cpa_commit();
    }

    // --- stage LUT (stride-20 remap), svals, sdims while copies fly ---
#pragma unroll
    for (int j = 0; j < 16; j++) {
        int i = j * TB + tid;                // 0..4095
        lut_s[(i >> 4) * LSTR + (i & 15)] = g_lut[i];
    }
    for (int i = tid; i < NC * NSPL * 8; i += TB) sval[i] = sval_g[i];
    if (tid < NC * NSPL) sdim[tid] = sdim_g[tid];

    cpa_wait0();
    __syncthreads();

    const int r = tid;
    if (base + r >= N) return;

    const float* arow = As + r * ND;
    const int rx = r & 15;

    unsigned long long acc[8];
#pragma unroll
    for (int j = 0; j < 8; j++) acc[j] = 0ull;

#pragma unroll
    for (int c = 0; c < NC; c++) {
        // encode: 4-level tree, exact fp32 compares (matches reference bit-for-bit)
        int g = 0;
#pragma unroll
        for (int i = 0; i < NSPL; i++) {
            int   d = sdim[c * NSPL + i];                          // uniform -> broadcast
            float x = arow[(((d >> 2) ^ rx) << 2) | (d & 3)];      // swizzled, <=2-way
            float v = sval[(c * NSPL + i) * 8 + g];
            g = (g << 1) + (x > v ? 1 : 0);
        }
        // gather: 4 x LDS.128, conflict-free; 8 packed f32x2 adds
        const ulonglong2* lr = (const ulonglong2*)(lut_s + (c * NK + g) * LSTR);
#pragma unroll
        for (int j = 0; j < 4; j++) {
            ulonglong2 v2 = lr[j];
            fadd2(acc[2 * j],     v2.x);
            fadd2(acc[2 * j + 1], v2.y);
        }
    }

    const long long n = base + r;
    const float2* accf = (const float2*)acc;
#pragma unroll
    for (int j = 0; j < 8; j++) {
        float2 p = accf[j];
        out[(long long)(2 * j)     * Nll + n] = p.x;
        out[(long long)(2 * j + 1) * Nll + n] = p.y;
    }
}

// ---------------------------------------------------------------------------
extern "C" void kernel_launch(void* const* d_in, const int* in_sizes, int n_in,
                              void* d_out, int out_size) {
    const float* A     = (const float*)d_in[0];
    const float* B     = (const float*)d_in[1];
    const float* P     = (const float*)d_in[2];
    const int*   sdims = (const int*)d_in[3];
    const float* svals = (const float*)d_in[4];
    float* out = (float*)d_out;
    int N = in_sizes[0] / ND;
    int ntiles = (N + TB - 1) / TB;

    lut_kernel<<<NC, 256>>>(B, P);

    size_t smem_bytes = (size_t)TB * ND * 4                       // A tile: 65536
                      + (size_t)(NC * NK * LSTR) * 4              // LUT:    20480
                      + (size_t)(NC * NSPL * 8) * 4               // svals:   2048
                      + (size_t)(NC * NSPL) * 4;                  // sdims:    256  -> 88320 B
    cudaFuncSetAttribute(maddness_kernel,
                         cudaFuncAttributeMaxDynamicSharedMemorySize,
                         (int)smem_bytes);

    maddness_kernel<<<ntiles, TB, smem_bytes>>>(A, sdims, svals, out, N);
}

// round 4
// speedup vs baseline: 1.2374x; 1.2374x over previous
#include <cuda_runtime.h>

#define NC 16       // codebooks
#define NK 16       // prototypes per codebook
#define NM 16       // output rows (M)
#define ND 64       // feature dim
#define NDP 65      // padded A row stride: bank=(r+d)%32 -> conflict-free encode reads
#define NSPL 4      // tree depth
#define LSTR 20     // LUT row stride: quad-bank (5g+j)%8 bijective -> conflict-free LDS.128
#define TB 256      // threads = rows per tile

__device__ float g_lut[NC * NK * NM];

// ---------------------------------------------------------------------------
// Kernel 1: lut[c,k,m] = sum_d B[m,d] * prototypes[c,k,d]
// ---------------------------------------------------------------------------
__global__ void lut_kernel(const float* __restrict__ B, const float* __restrict__ P) {
    __shared__ float Bs[NM][ND + 1];
    __shared__ float Ps[NK][ND + 1];
    int c = blockIdx.x, tid = threadIdx.x;
    for (int i = tid; i < NM * ND; i += 256) Bs[i >> 6][i & 63] = B[i];
    for (int i = tid; i < NK * ND; i += 256) Ps[i >> 6][i & 63] = P[c * NK * ND + i];
    __syncthreads();
    int k = tid >> 4, m = tid & 15;
    float acc = 0.f;
#pragma unroll
    for (int d = 0; d < ND; d++) acc = fmaf(Bs[m][d], Ps[k][d], acc);
    g_lut[(c * NK + k) * NM + m] = acc;
}

__device__ __forceinline__ void fadd2(unsigned long long& a, unsigned long long b) {
    asm("add.rn.f32x2 %0, %0, %1;" : "+l"(a) : "l"(b));
}

// ---------------------------------------------------------------------------
// Kernel 2: one 256-row tile per CTA, 2 CTAs/SM.
//  - A staged at row stride 65 -> encode reads perfectly conflict-free
//  - branchless select-tree encode (no serial LDS chain; pure ALU after
//    5 uniform broadcast loads per codebook)
//  - LUT gather: stride-20 LDS.128, conflict-free; packed f32x2 accumulate
// ---------------------------------------------------------------------------
__global__ void __launch_bounds__(TB, 2) maddness_kernel(
    const float* __restrict__ A,
    const int*   __restrict__ sdim_g,   // [C,NSPL]
    const float* __restrict__ sval_g,   // [C,NSPL,8]
    float*       __restrict__ out,      // [M,N]
    int N)
{
    extern __shared__ float smem[];
    float* As    = smem;                              // TB*NDP floats (66560B)
    float* lut_s = As + TB * NDP;                     // 5120 floats (16B-aligned)
    float* sval  = lut_s + NC * NK * LSTR;            // 512 floats
    int*   sdim  = (int*)(sval + NC * NSPL * 8);      // 64 ints

    const int tid = threadIdx.x;
    const long long base = (long long)blockIdx.x * TB;
    const long long Nll = N;

    // --- A tile: LDG.128 coalesced, scatter into padded-65 layout ---
    {
        const float4* gb = (const float4*)(A + base * ND);
#pragma unroll
        for (int j = 0; j < 16; j++) {
            int idx4 = j * TB + tid;          // float4 index within tile
            int r    = idx4 >> 4;             // row 0..255
            int c4   = idx4 & 15;             // 16B chunk 0..15
            if (base + r < N) {
                float4 v = gb[idx4];
                float* p = As + r * NDP + (c4 << 2);
                p[0] = v.x; p[1] = v.y; p[2] = v.z; p[3] = v.w;
            }
        }
    }

    // --- stage LUT (stride-20 remap), svals, sdims ---
#pragma unroll
    for (int j = 0; j < 16; j++) {
        int i = j * TB + tid;                 // 0..4095
        lut_s[(i >> 4) * LSTR + (i & 15)] = g_lut[i];
    }
    for (int i = tid; i < NC * NSPL * 8; i += TB) sval[i] = sval_g[i];
    if (tid < NC * NSPL) sdim[tid] = sdim_g[tid];

    __syncthreads();

    const int r = tid;
    if (base + r >= N) return;

    const float* arow = As + r * NDP;

    unsigned long long acc[8];
#pragma unroll
    for (int j = 0; j < 8; j++) acc[j] = 0ull;

#pragma unroll 4
    for (int c = 0; c < NC; c++) {
        // uniform (broadcast) loads: 4 split dims + 15 candidate split values
        const int4 sd = *(const int4*)(sdim + c * 4);
        const float*  sb = sval + c * 32;
        const float   s0  = sb[0];
        const float2  s1  = *(const float2*)(sb + 8);
        const float4  s2  = *(const float4*)(sb + 16);
        const float4  s3a = *(const float4*)(sb + 24);
        const float4  s3b = *(const float4*)(sb + 28);

        // conflict-free x reads (independent of tree path)
        const float x0 = arow[sd.x];
        const float x1 = arow[sd.y];
        const float x2 = arow[sd.z];
        const float x3 = arow[sd.w];

        // branchless tree descent — same compares as reference
        const bool  b0 = x0 > s0;
        const float v1 = b0 ? s1.y : s1.x;
        const bool  b1 = x1 > v1;
        const float t0 = b0 ? s2.z : s2.x;
        const float t1 = b0 ? s2.w : s2.y;
        const float v2 = b1 ? t1 : t0;
        const bool  b2 = x2 > v2;
        const float u0 = b0 ? s3b.x : s3a.x;
        const float u1 = b0 ? s3b.y : s3a.y;
        const float u2 = b0 ? s3b.z : s3a.z;
        const float u3 = b0 ? s3b.w : s3a.w;
        const float w0 = b1 ? u2 : u0;
        const float w1 = b1 ? u3 : u1;
        const float v3 = b2 ? w1 : w0;
        const bool  b3 = x3 > v3;
        const int g = (((((int)b0 << 1) | (int)b1) << 1) | (int)b2) << 1 | (int)b3;

        // gather: 4 x LDS.128 conflict-free; 8 packed f32x2 adds
        const ulonglong2* lr = (const ulonglong2*)(lut_s + (c * NK + g) * LSTR);
#pragma unroll
        for (int j = 0; j < 4; j++) {
            ulonglong2 v2q = lr[j];
            fadd2(acc[2 * j],     v2q.x);
            fadd2(acc[2 * j + 1], v2q.y);
        }
    }

    const long long n = base + r;
    const float2* accf = (const float2*)acc;
#pragma unroll
    for (int j = 0; j < 8; j++) {
        float2 p = accf[j];
        out[(long long)(2 * j)     * Nll + n] = p.x;
        out[(long long)(2 * j + 1) * Nll + n] = p.y;
    }
}

// ---------------------------------------------------------------------------
extern "C" void kernel_launch(void* const* d_in, const int* in_sizes, int n_in,
                              void* d_out, int out_size) {
    const float* A     = (const float*)d_in[0];
    const float* B     = (const float*)d_in[1];
    const float* P     = (const float*)d_in[2];
    const int*   sdims = (const int*)d_in[3];
    const float* svals = (const float*)d_in[4];
    float* out = (float*)d_out;
    int N = in_sizes[0] / ND;
    int ntiles = (N + TB - 1) / TB;

    lut_kernel<<<NC, 256>>>(B, P);

    size_t smem_bytes = (size_t)TB * NDP * 4                      // A tile: 66560
                      + (size_t)(NC * NK * LSTR) * 4              // LUT:    20480
                      + (size_t)(NC * NSPL * 8) * 4               // svals:   2048
                      + (size_t)(NC * NSPL) * 4;                  // sdims:    256  -> 89344 B
    cudaFuncSetAttribute(maddness_kernel,
                         cudaFuncAttributeMaxDynamicSharedMemorySize,
                         (int)smem_bytes);

    maddness_kernel<<<ntiles, TB, smem_bytes>>>(A, sdims, svals, out, N);
}

// round 5
// speedup vs baseline: 1.2475x; 1.0082x over previous
#include <cuda_runtime.h>

#define NC 16       // codebooks
#define NK 16       // prototypes per codebook
#define NM 16       // output rows (M)
#define ND 64       // feature dim
#define NDP 65      // padded A row stride: bank=(r+d)%32 -> conflict-free encode reads
#define NSPL 4      // tree depth
#define LSTR 20     // LUT row stride: conflict-free LDS.128 gather
#define TBE 128     // encode: rows per tile
#define TBG 256     // gather: rows per tile

__device__ float g_lut[NC * NK * NM];
__device__ unsigned long long g_codes[1 << 18];   // 262144 rows max, 2MB

// ---------------------------------------------------------------------------
// Kernel 1: lut[c,k,m] = sum_d B[m,d] * prototypes[c,k,d]
// ---------------------------------------------------------------------------
__global__ void lut_kernel(const float* __restrict__ B, const float* __restrict__ P) {
    __shared__ float Bs[NM][ND + 1];
    __shared__ float Ps[NK][ND + 1];
    int c = blockIdx.x, tid = threadIdx.x;
    for (int i = tid; i < NM * ND; i += 256) Bs[i >> 6][i & 63] = B[i];
    for (int i = tid; i < NK * ND; i += 256) Ps[i >> 6][i & 63] = P[c * NK * ND + i];
    __syncthreads();
    int k = tid >> 4, m = tid & 15;
    float acc = 0.f;
#pragma unroll
    for (int d = 0; d < ND; d++) acc = fmaf(Bs[m][d], Ps[k][d], acc);
    g_lut[(c * NK + k) * NM + m] = acc;
}

__device__ __forceinline__ void fadd2(unsigned long long& a, unsigned long long b) {
    asm("add.rn.f32x2 %0, %0, %1;" : "+l"(a) : "l"(b));
}

// ---------------------------------------------------------------------------
// Kernel 2 (encode): 128-row tile, 6 CTAs/SM. Branchless tree encode;
// writes 16x4-bit packed code per row.
// ---------------------------------------------------------------------------
__global__ void __launch_bounds__(TBE, 6) encode_kernel(
    const float* __restrict__ A,
    const int*   __restrict__ sdim_g,   // [C,NSPL]
    const float* __restrict__ sval_g,   // [C,NSPL,8]
    int N)
{
    __shared__ float As[TBE * NDP];       // 33280B
    __shared__ float sval16[NC * 16];     // repacked: s0,s1x,s1y,pad | s2(4) | s3(8)
    __shared__ int   sdim[NC * NSPL];

    const int tid  = threadIdx.x;
    const long long base = (long long)blockIdx.x * TBE;

    // --- stage A: warp handles 4 rows x 8 chunks; LDG fully coalesced,
    //     STS banks (dr + 4*c8 + r0) cover all 32 -> conflict-free ---
    {
        const int w = tid >> 5, lane = tid & 31;
        const int dr = lane >> 3, c8 = lane & 7;
        const float4* gb = (const float4*)(A + base * ND);
#pragma unroll
        for (int jr = 0; jr < 8; jr++) {
            int r = jr * 16 + w * 4 + dr;
            bool ok = (base + r < N);
#pragma unroll
            for (int jc = 0; jc < 2; jc++) {
                int c4 = jc * 8 + c8;
                if (ok) {
                    float4 v = gb[r * 16 + c4];
                    float* p = As + r * NDP + (c4 << 2);
                    p[0] = v.x; p[1] = v.y; p[2] = v.z; p[3] = v.w;
                }
            }
        }
    }

    // --- stage repacked split-vals + dims ---
    for (int i = tid; i < NC * 16; i += TBE) {
        int cb = i >> 4, j = i & 15;
        int src = (j == 0) ? 0 : (j == 1) ? 8 : (j == 2) ? 9 : (j == 3) ? 0
                : (j < 8) ? (12 + j) : (16 + j);
        sval16[i] = sval_g[cb * 32 + src];
    }
    if (tid < NC * NSPL) sdim[tid] = sdim_g[tid];
    __syncthreads();

    const int r = tid;
    if (base + r >= N) return;
    const float* arow = As + r * NDP;

    unsigned long long code = 0ull;
#pragma unroll
    for (int c = 0; c < NC; c++) {
        const int4   sd  = ((const int4*)sdim)[c];
        const float4 q0  = ((const float4*)sval16)[c * 4 + 0]; // s0, s1x, s1y, pad
        const float4 s2  = ((const float4*)sval16)[c * 4 + 1];
        const float4 s3a = ((const float4*)sval16)[c * 4 + 2];
        const float4 s3b = ((const float4*)sval16)[c * 4 + 3];

        const float x0 = arow[sd.x];
        const float x1 = arow[sd.y];
        const float x2 = arow[sd.z];
        const float x3 = arow[sd.w];

        const bool  b0 = x0 > q0.x;
        const float v1 = b0 ? q0.z : q0.y;
        const bool  b1 = x1 > v1;
        const float t0 = b0 ? s2.z : s2.x;
        const float t1 = b0 ? s2.w : s2.y;
        const float v2 = b1 ? t1 : t0;
        const bool  b2 = x2 > v2;
        const float u0 = b0 ? s3b.x : s3a.x;
        const float u1 = b0 ? s3b.y : s3a.y;
        const float u2 = b0 ? s3b.z : s3a.z;
        const float u3 = b0 ? s3b.w : s3a.w;
        const float w0 = b1 ? u2 : u0;
        const float w1 = b1 ? u3 : u1;
        const float v3 = b2 ? w1 : w0;
        const bool  b3 = x3 > v3;

        const unsigned long long g =
            (unsigned long long)((((((int)b0 << 1) | (int)b1) << 1) | (int)b2) << 1 | (int)b3);
        code |= g << (4 * c);
    }
    g_codes[base + r] = code;
}

// ---------------------------------------------------------------------------
// Kernel 3 (gather): LUT-only smem (20.5KB) -> 40 warps/SM. Per row: unpack
// code, 16 x (4 LDS.128 conflict-free gather + f32x2 accumulate).
// ---------------------------------------------------------------------------
__global__ void __launch_bounds__(TBG, 5) gather_kernel(
    float* __restrict__ out, int N)
{
    __shared__ float lut_s[NC * NK * LSTR];   // 20480B

    const int tid = threadIdx.x;
#pragma unroll
    for (int j = 0; j < 16; j++) {
        int i = j * TBG + tid;                 // 0..4095
        lut_s[(i >> 4) * LSTR + (i & 15)] = g_lut[i];
    }
    __syncthreads();

    const long long n = (long long)blockIdx.x * TBG + tid;
    if (n >= N) return;

    const unsigned long long code = g_codes[n];

    unsigned long long acc[8];
#pragma unroll
    for (int j = 0; j < 8; j++) acc[j] = 0ull;

#pragma unroll
    for (int c = 0; c < NC; c++) {
        const int g = (int)((code >> (4 * c)) & 15ull);
        const ulonglong2* lr = (const ulonglong2*)(lut_s + (c * NK + g) * LSTR);
#pragma unroll
        for (int j = 0; j < 4; j++) {
            ulonglong2 v = lr[j];
            fadd2(acc[2 * j],     v.x);
            fadd2(acc[2 * j + 1], v.y);
        }
    }

    const long long Nll = N;
    const float2* accf = (const float2*)acc;
#pragma unroll
    for (int j = 0; j < 8; j++) {
        float2 p = accf[j];
        out[(long long)(2 * j)     * Nll + n] = p.x;
        out[(long long)(2 * j + 1) * Nll + n] = p.y;
    }
}

// ---------------------------------------------------------------------------
extern "C" void kernel_launch(void* const* d_in, const int* in_sizes, int n_in,
                              void* d_out, int out_size) {
    const float* A     = (const float*)d_in[0];
    const float* B     = (const float*)d_in[1];
    const float* P     = (const float*)d_in[2];
    const int*   sdims = (const int*)d_in[3];
    const float* svals = (const float*)d_in[4];
    float* out = (float*)d_out;
    int N = in_sizes[0] / ND;

    lut_kernel<<<NC, 256>>>(B, P);
    encode_kernel<<<(N + TBE - 1) / TBE, TBE>>>(A, sdims, svals, N);
    gather_kernel<<<(N + TBG - 1) / TBG, TBG>>>(out, N);
}

// round 6
// speedup vs baseline: 1.3244x; 1.0616x over previous
#include <cuda_runtime.h>

#define NC 16       // codebooks
#define NK 16       // prototypes per codebook
#define NM 16       // output rows (M)
#define ND 64       // feature dim
#define NDP 65      // padded A row stride: bank=(r+d)%32 -> conflict-free encode reads
#define NSPL 4      // tree depth
#define LSTR 20     // LUT row stride: conflict-free LDS.128 gather
#define TBE 128     // encode: rows per tile
#define TBG 128     // gather: threads (2 rows each -> 256 rows/tile)

__device__ float g_lut[NC * NK * NM];
__device__ unsigned long long g_codes[1 << 18];   // 262144 rows, 2MB

__device__ __forceinline__ void fadd2(unsigned long long& a, unsigned long long b) {
    asm("add.rn.f32x2 %0, %0, %1;" : "+l"(a) : "l"(b));
}

// ---------------------------------------------------------------------------
// Kernel A (encode + lut fused in one launch):
//   blocks [0, ntiles)        : encode 128 rows -> packed 64-bit code/row
//   blocks [ntiles, ntiles+16): lut[c,k,m] = sum_d B[m,d]*P[c,k,d]
// ---------------------------------------------------------------------------
__global__ void __launch_bounds__(TBE, 6) encode_kernel(
    const float* __restrict__ A,
    const float* __restrict__ B,        // [M,D]
    const float* __restrict__ P,        // [C,K,D]
    const int*   __restrict__ sdim_g,   // [C,NSPL]
    const float* __restrict__ sval_g,   // [C,NSPL,8]
    int N, int ntiles)
{
    __shared__ float As[TBE * NDP];       // 33280B (reused as Bs/Ps by lut blocks)
    __shared__ float sval16[NC * 16];
    __shared__ int   sdim[NC * NSPL];

    const int tid = threadIdx.x;

    if (blockIdx.x >= ntiles) {
        // ---- LUT block: one codebook c ----
        int c = blockIdx.x - ntiles;
        float* Bs = As;                       // [NM][ND+1]
        float* Ps = As + NM * (ND + 1);       // [NK][ND+1]
        for (int i = tid; i < NM * ND; i += TBE) Bs[(i >> 6) * (ND + 1) + (i & 63)] = B[i];
        for (int i = tid; i < NK * ND; i += TBE) Ps[(i >> 6) * (ND + 1) + (i & 63)] = P[c * NK * ND + i];
        __syncthreads();
#pragma unroll
        for (int e = 0; e < 2; e++) {
            int i = e * TBE + tid;            // 0..255
            int k = i >> 4, m = i & 15;
            float acc = 0.f;
#pragma unroll
            for (int d = 0; d < ND; d++)
                acc = fmaf(Bs[m * (ND + 1) + d], Ps[k * (ND + 1) + d], acc);
            g_lut[(c * NK + k) * NM + m] = acc;
        }
        return;
    }

    const long long base = (long long)blockIdx.x * TBE;

    // --- stage A: warp = 4 rows x 8 chunks; coalesced LDG.128, conflict-free STS ---
    {
        const int w = tid >> 5, lane = tid & 31;
        const int dr = lane >> 3, c8 = lane & 7;
        const float4* gb = (const float4*)(A + base * ND);
#pragma unroll
        for (int jr = 0; jr < 8; jr++) {
            int r = jr * 16 + w * 4 + dr;
            bool ok = (base + r < N);
#pragma unroll
            for (int jc = 0; jc < 2; jc++) {
                int c4 = jc * 8 + c8;
                if (ok) {
                    float4 v = gb[r * 16 + c4];
                    float* p = As + r * NDP + (c4 << 2);
                    p[0] = v.x; p[1] = v.y; p[2] = v.z; p[3] = v.w;
                }
            }
        }
    }

    // --- stage repacked split-vals + dims ---
    for (int i = tid; i < NC * 16; i += TBE) {
        int cb = i >> 4, j = i & 15;
        int src = (j == 0) ? 0 : (j == 1) ? 8 : (j == 2) ? 9 : (j == 3) ? 0
                : (j < 8) ? (12 + j) : (16 + j);
        sval16[i] = sval_g[cb * 32 + src];
    }
    if (tid < NC * NSPL) sdim[tid] = sdim_g[tid];
    __syncthreads();

    const int r = tid;
    if (base + r >= N) return;
    const float* arow = As + r * NDP;

    unsigned long long code = 0ull;
#pragma unroll
    for (int c = 0; c < NC; c++) {
        const int4   sd  = ((const int4*)sdim)[c];
        const float4 q0  = ((const float4*)sval16)[c * 4 + 0]; // s0, s1x, s1y, pad
        const float4 s2  = ((const float4*)sval16)[c * 4 + 1];
        const float4 s3a = ((const float4*)sval16)[c * 4 + 2];
        const float4 s3b = ((const float4*)sval16)[c * 4 + 3];

        const float x0 = arow[sd.x];
        const float x1 = arow[sd.y];
        const float x2 = arow[sd.z];
        const float x3 = arow[sd.w];

        const bool  b0 = x0 > q0.x;
        const float v1 = b0 ? q0.z : q0.y;
        const bool  b1 = x1 > v1;
        const float t0 = b0 ? s2.z : s2.x;
        const float t1 = b0 ? s2.w : s2.y;
        const float v2 = b1 ? t1 : t0;
        const bool  b2 = x2 > v2;
        const float u0 = b0 ? s3b.x : s3a.x;
        const float u1 = b0 ? s3b.y : s3a.y;
        const float u2 = b0 ? s3b.z : s3a.z;
        const float u3 = b0 ? s3b.w : s3a.w;
        const float w0 = b1 ? u2 : u0;
        const float w1 = b1 ? u3 : u1;
        const float v3 = b2 ? w1 : w0;
        const bool  b3 = x3 > v3;

        const unsigned long long g =
            (unsigned long long)((((((int)b0 << 1) | (int)b1) << 1) | (int)b2) << 1 | (int)b3);
        code |= g << (4 * c);
    }
    g_codes[base + r] = code;
}

// ---------------------------------------------------------------------------
// Kernel B (gather): 2 rows/thread, LUT-only smem (20.5KB), 5 CTAs/SM.
// Per cb: 8 x LDS.128 (two independent rows) + 16 packed f32x2 adds.
// ---------------------------------------------------------------------------
__global__ void __launch_bounds__(TBG, 5) gather_kernel(
    float* __restrict__ out, int N)
{
    __shared__ float lut_s[NC * NK * LSTR];   // 20480B

    const int tid = threadIdx.x;
#pragma unroll
    for (int j = 0; j < 32; j++) {
        int i = j * TBG + tid;                 // 0..4095
        lut_s[(i >> 4) * LSTR + (i & 15)] = g_lut[i];
    }
    __syncthreads();

    const long long base = (long long)blockIdx.x * (2 * TBG);
    const long long n0 = base + tid;
    const long long n1 = base + tid + TBG;
    const bool ok0 = n0 < N, ok1 = n1 < N;

    const unsigned long long code0 = ok0 ? g_codes[n0] : 0ull;
    const unsigned long long code1 = ok1 ? g_codes[n1] : 0ull;

    unsigned long long acc0[8], acc1[8];
#pragma unroll
    for (int j = 0; j < 8; j++) { acc0[j] = 0ull; acc1[j] = 0ull; }

#pragma unroll
    for (int c = 0; c < NC; c++) {
        const int g0 = (int)((code0 >> (4 * c)) & 15ull);
        const int g1 = (int)((code1 >> (4 * c)) & 15ull);
        const ulonglong2* lr0 = (const ulonglong2*)(lut_s + (c * NK + g0) * LSTR);
        const ulonglong2* lr1 = (const ulonglong2*)(lut_s + (c * NK + g1) * LSTR);
#pragma unroll
        for (int j = 0; j < 4; j++) {
            ulonglong2 v0 = lr0[j];
            ulonglong2 v1 = lr1[j];
            fadd2(acc0[2 * j],     v0.x);
            fadd2(acc0[2 * j + 1], v0.y);
            fadd2(acc1[2 * j],     v1.x);
            fadd2(acc1[2 * j + 1], v1.y);
        }
    }

    const long long Nll = N;
    const float2* a0 = (const float2*)acc0;
    const float2* a1 = (const float2*)acc1;
    if (ok0) {
#pragma unroll
        for (int j = 0; j < 8; j++) {
            float2 p = a0[j];
            out[(long long)(2 * j)     * Nll + n0] = p.x;
            out[(long long)(2 * j + 1) * Nll + n0] = p.y;
        }
    }
    if (ok1) {
#pragma unroll
        for (int j = 0; j < 8; j++) {
            float2 p = a1[j];
            out[(long long)(2 * j)     * Nll + n1] = p.x;
            out[(long long)(2 * j + 1) * Nll + n1] = p.y;
        }
    }
}

// ---------------------------------------------------------------------------
extern "C" void kernel_launch(void* const* d_in, const int* in_sizes, int n_in,
                              void* d_out, int out_size) {
    const float* A     = (const float*)d_in[0];
    const float* B     = (const float*)d_in[1];
    const float* P     = (const float*)d_in[2];
    const int*   sdims = (const int*)d_in[3];
    const float* svals = (const float*)d_in[4];
    float* out = (float*)d_out;
    int N = in_sizes[0] / ND;

    int ntiles = (N + TBE - 1) / TBE;
    encode_kernel<<<ntiles + NC, TBE>>>(A, B, P, sdims, svals, N, ntiles);
    gather_kernel<<<(N + 2 * TBG - 1) / (2 * TBG), TBG>>>(out, N);
}